// round 12
// baseline (speedup 1.0000x reference)
#include <cuda_runtime.h>
#include <cuda_fp16.h>
#include <cstdint>

#define N_BLOCKS   512
#define BLOCK_IN   128
#define BLOCK_OUT  128
#define LAYER_IN   65536
#define LAYER_OUT  65536
#define BATCH      2048

// softmax(c) as fp16, row-major [n][m][o]  (m = K dim, o = N dim)
__device__ __align__(16) __half g_w[(size_t)N_BLOCKS * BLOCK_IN * BLOCK_OUT];

__device__ __forceinline__ uint32_t smem_u32(const void* p) {
    uint32_t a;
    asm("{ .reg .u64 t; cvta.to.shared.u64 t, %1; cvt.u32.u64 %0, t; }" : "=r"(a) : "l"(p));
    return a;
}

// ---------------------------------------------------------------------------
// Pass 1: softmax over m for each (n, o); write fp16 w[m][o].  (unchanged)
// ---------------------------------------------------------------------------
__global__ __launch_bounds__(512) void softmax_kernel(const float* __restrict__ c) {
    extern __shared__ float sm[];
    float* se   = sm;
    float* psum = sm + 16384;

    const int n  = blockIdx.x;
    const int tid = threadIdx.x;
    const int o4 = (tid & 31) * 4;
    const int q  = tid >> 5;
    const float* cn = c + (size_t)n * (BLOCK_IN * BLOCK_OUT);

    float4 s = make_float4(0.f, 0.f, 0.f, 0.f);
#pragma unroll
    for (int j = 0; j < 8; j++) {
        int m = q * 8 + j;
        float4 v = *(const float4*)(cn + m * 128 + o4);
        float4 e = make_float4(__expf(v.x), __expf(v.y), __expf(v.z), __expf(v.w));
        *(float4*)(se + m * 128 + o4) = e;
        s.x += e.x; s.y += e.y; s.z += e.z; s.w += e.w;
    }
    *(float4*)(psum + q * 128 + o4) = s;
    __syncthreads();

    float4 tot = make_float4(0.f, 0.f, 0.f, 0.f);
#pragma unroll
    for (int k = 0; k < 16; k++) {
        float4 p = *(const float4*)(psum + k * 128 + o4);
        tot.x += p.x; tot.y += p.y; tot.z += p.z; tot.w += p.w;
    }
    float4 inv = make_float4(1.f / tot.x, 1.f / tot.y, 1.f / tot.z, 1.f / tot.w);

    __half* w = g_w + (size_t)n * (BLOCK_IN * BLOCK_OUT);
#pragma unroll
    for (int j = 0; j < 8; j++) {
        int m = q * 8 + j;
        float4 e = *(const float4*)(se + m * 128 + o4);
        __half2 h01 = __floats2half2_rn(e.x * inv.x, e.y * inv.y);
        __half2 h23 = __floats2half2_rn(e.z * inv.z, e.w * inv.w);
        uint2 pk = make_uint2(*(uint32_t*)&h01, *(uint32_t*)&h23);
        *(uint2*)(w + m * 128 + o4) = pk;
    }
}

// ---------------------------------------------------------------------------
// Pass 2: cp.async GEMM, A fragments read DIRECTLY from fp32 stage (no fp16
// sA, no convert phase). 256 threads, 8 warps, warp tile 64x32. Double-
// buffered fp32 stage (padded rows), fp16 sB via ldmatrix.trans.
// ---------------------------------------------------------------------------
#define LDS_F 132                        // floats per padded stage row
#define STAGE_FLOATS (128 * LDS_F)       // 16896 floats = 67584 B per buffer
#define LDA 136                          // halfs per padded sB row
#define SB_HALFS (128 * LDA)
#define SMEM_TOTAL (2 * STAGE_FLOATS * 4 + SB_HALFS * 2)   // 169984 B
#define BT_PER_CTA 8

#define LDSM_X4_T(R0, R1, R2, R3, ADDR)                                        \
    asm volatile("ldmatrix.sync.aligned.m8n8.x4.trans.shared.b16 {%0,%1,%2,%3}, [%4];" \
                 : "=r"(R0), "=r"(R1), "=r"(R2), "=r"(R3) : "r"(ADDR))

#define MMA16816(D, A, B0, B1)                                                 \
    asm volatile("mma.sync.aligned.m16n8k16.row.col.f32.f16.f16.f32 "          \
                 "{%0,%1,%2,%3}, {%4,%5,%6,%7}, {%8,%9}, {%0,%1,%2,%3};"       \
                 : "+f"((D)[0]), "+f"((D)[1]), "+f"((D)[2]), "+f"((D)[3])      \
                 : "r"((A)[0]), "r"((A)[1]), "r"((A)[2]), "r"((A)[3]),         \
                   "r"(B0), "r"(B1))

__device__ __forceinline__ void cp16(uint32_t dst_smem, const void* src) {
    asm volatile("cp.async.cg.shared.global [%0], [%1], 16;" :: "r"(dst_smem), "l"(src));
}
#define CP_COMMIT() asm volatile("cp.async.commit_group;" ::: "memory")
#define CP_WAIT0()  asm volatile("cp.async.wait_group 0;" ::: "memory")

__device__ __forceinline__ uint32_t pack_h2(float lo, float hi) {
    uint32_t r;
    asm("cvt.rn.f16x2.f32 %0, %1, %2;" : "=r"(r) : "f"(hi), "f"(lo));
    return r;
}

// x tile [128 rows x 128 k] fp32 -> padded stage, 16 cp.asyncs per thread
__device__ __forceinline__ void stage_x(const float* __restrict__ xb, uint32_t stage_s, int tid) {
#pragma unroll
    for (int i = 0; i < 16; i++) {
        int idx = tid + i * 256;               // 0..4095 (16B chunks)
        int r   = idx >> 5;
        int k4  = (idx & 31) << 2;
        cp16(stage_s + (r * LDS_F + k4) * 4, xb + (size_t)r * LAYER_IN + k4);
    }
}

__global__ __launch_bounds__(256, 1)
void gemm_kernel(const float* __restrict__ x, float* __restrict__ out) {
    extern __shared__ char smem[];
    float* stg[2] = { (float*)smem, (float*)smem + STAGE_FLOATS };
    __half* sB = (__half*)(smem + 2 * STAGE_FLOATS * 4);
    const uint32_t stg_s[2] = { smem_u32(stg[0]), smem_u32(stg[1]) };

    const int tid  = threadIdx.x;
    const int wid  = tid >> 5;
    const int lane = tid & 31;
    const int n    = blockIdx.x;
    const int btg  = blockIdx.y;

    const float* xcol = x + (size_t)n * 128;
    const __half* wsrc = g_w + (size_t)n * (BLOCK_IN * BLOCK_OUT);

    // ---- prologue: cp.async w -> sB and x(tile0) -> stage0 ----
    {
        uint32_t sB_s = smem_u32(sB);
#pragma unroll
        for (int i = 0; i < 8; i++) {
            int idx = tid + i * 256;           // 0..2047
            int r   = idx >> 4;
            int c   = (idx & 15) << 3;
            cp16(sB_s + (r * LDA + c) * 2, wsrc + idx * 8);
        }
    }
    stage_x(xcol + (size_t)(btg * BT_PER_CTA * 128) * LAYER_IN, stg_s[0], tid);
    CP_COMMIT();
    CP_WAIT0();
    __syncthreads();

    // 8 warps: 2 (m) x 4 (n); warp tile 64x32
    const int warp_m = wid & 1;
    const int warp_n = wid >> 1;
    const int lr = lane & 15;
    const int lc = (lane >> 4) << 3;
    const int ag = lane >> 2;                  // A-frag group row 0..7
    const int at = (lane & 3) << 1;            // A-frag col pair base

    for (int t = 0; t < BT_PER_CTA; t++) {
        const int bt = btg * BT_PER_CTA + t;
        const float* stage = stg[t & 1];

        // ---- prefetch next x tile into the other stage buffer ----
        if (t + 1 < BT_PER_CTA) {
            stage_x(xcol + (size_t)((bt + 1) * 128) * LAYER_IN, stg_s[(t + 1) & 1], tid);
            CP_COMMIT();
        }

        float acc[4][4][4];
#pragma unroll
        for (int mt = 0; mt < 4; mt++)
#pragma unroll
            for (int nt = 0; nt < 4; nt++)
#pragma unroll
                for (int j = 0; j < 4; j++) acc[mt][nt][j] = 0.f;

#pragma unroll
        for (int ks = 0; ks < 8; ks++) {
            const int k = ks * 16;

            // A fragments straight from fp32 stage: LDS.64 + cvt per reg
            uint32_t a[4][4];
#pragma unroll
            for (int mt = 0; mt < 4; mt++) {
                int r0 = warp_m * 64 + mt * 16 + ag;
                int c0 = k + at;
                float2 v00 = *(const float2*)(stage + r0 * LDS_F + c0);
                float2 v10 = *(const float2*)(stage + (r0 + 8) * LDS_F + c0);
                float2 v01 = *(const float2*)(stage + r0 * LDS_F + c0 + 8);
                float2 v11 = *(const float2*)(stage + (r0 + 8) * LDS_F + c0 + 8);
                a[mt][0] = pack_h2(v00.x, v00.y);
                a[mt][1] = pack_h2(v10.x, v10.y);
                a[mt][2] = pack_h2(v01.x, v01.y);
                a[mt][3] = pack_h2(v11.x, v11.y);
            }

            uint32_t b[4][2];
#pragma unroll
            for (int qq = 0; qq < 2; qq++) {
                int nn = warp_n * 32 + qq * 16;
                uint32_t addr = smem_u32(&sB[(k + lr) * LDA + nn + lc]);
                LDSM_X4_T(b[qq * 2][0], b[qq * 2][1], b[qq * 2 + 1][0], b[qq * 2 + 1][1], addr);
            }

#pragma unroll
            for (int mt = 0; mt < 4; mt++)
#pragma unroll
                for (int nt = 0; nt < 4; nt++)
                    MMA16816(acc[mt][nt], a[mt], b[nt][0], b[nt][1]);
        }

        // next tile landed + all warps done reading this stage buffer
        CP_WAIT0();
        __syncthreads();

        // ---- epilogue: coalesced float2 stores (drain under next k-loop) ----
        float* obase = out + (size_t)(bt * 128) * LAYER_OUT + (size_t)n * 128;
        const int er = lane >> 2;
        const int ec = (lane & 3) << 1;
#pragma unroll
        for (int mt = 0; mt < 4; mt++) {
#pragma unroll
            for (int nt = 0; nt < 4; nt++) {
                int r0 = warp_m * 64 + mt * 16 + er;
                int c0 = warp_n * 32 + nt * 8 + ec;
                *(float2*)(obase + (size_t)r0 * LAYER_OUT + c0) =
                    make_float2(acc[mt][nt][0], acc[mt][nt][1]);
                *(float2*)(obase + (size_t)(r0 + 8) * LAYER_OUT + c0) =
                    make_float2(acc[mt][nt][2], acc[mt][nt][3]);
            }
        }
    }
}

// ---------------------------------------------------------------------------
extern "C" void kernel_launch(void* const* d_in, const int* in_sizes, int n_in,
                              void* d_out, int out_size) {
    (void)in_sizes; (void)n_in; (void)out_size;
    const float* x = (const float*)d_in[0];
    const float* c = (const float*)d_in[1];
    float* out = (float*)d_out;

    cudaFuncSetAttribute(softmax_kernel, cudaFuncAttributeMaxDynamicSharedMemorySize, 73728);
    cudaFuncSetAttribute(gemm_kernel,    cudaFuncAttributeMaxDynamicSharedMemorySize, SMEM_TOTAL);

    softmax_kernel<<<N_BLOCKS, 512, 73728>>>(c);
    gemm_kernel<<<dim3(N_BLOCKS, BATCH / 128 / BT_PER_CTA), 256, SMEM_TOTAL>>>(x, out);
}

// round 13
// speedup vs baseline: 2.0135x; 2.0135x over previous
#include <cuda_runtime.h>
#include <cuda_fp16.h>
#include <cstdint>

#define N_BLOCKS   512
#define BLOCK_IN   128
#define BLOCK_OUT  128
#define LAYER_IN   65536
#define LAYER_OUT  65536
#define BATCH      2048

// softmax(c) as fp16, row-major [n][m][o]  (m = K dim, o = N dim)
__device__ __align__(16) __half g_w[(size_t)N_BLOCKS * BLOCK_IN * BLOCK_OUT];

__device__ __forceinline__ uint32_t smem_u32(const void* p) {
    uint32_t a;
    asm("{ .reg .u64 t; cvta.to.shared.u64 t, %1; cvt.u32.u64 %0, t; }" : "=r"(a) : "l"(p));
    return a;
}

// ---------------------------------------------------------------------------
// Pass 1: softmax over m for each (n, o); write fp16 w[m][o].  (unchanged)
// ---------------------------------------------------------------------------
__global__ __launch_bounds__(512) void softmax_kernel(const float* __restrict__ c) {
    extern __shared__ float sm[];
    float* se   = sm;
    float* psum = sm + 16384;

    const int n  = blockIdx.x;
    const int tid = threadIdx.x;
    const int o4 = (tid & 31) * 4;
    const int q  = tid >> 5;
    const float* cn = c + (size_t)n * (BLOCK_IN * BLOCK_OUT);

    float4 s = make_float4(0.f, 0.f, 0.f, 0.f);
#pragma unroll
    for (int j = 0; j < 8; j++) {
        int m = q * 8 + j;
        float4 v = *(const float4*)(cn + m * 128 + o4);
        float4 e = make_float4(__expf(v.x), __expf(v.y), __expf(v.z), __expf(v.w));
        *(float4*)(se + m * 128 + o4) = e;
        s.x += e.x; s.y += e.y; s.z += e.z; s.w += e.w;
    }
    *(float4*)(psum + q * 128 + o4) = s;
    __syncthreads();

    float4 tot = make_float4(0.f, 0.f, 0.f, 0.f);
#pragma unroll
    for (int k = 0; k < 16; k++) {
        float4 p = *(const float4*)(psum + k * 128 + o4);
        tot.x += p.x; tot.y += p.y; tot.z += p.z; tot.w += p.w;
    }
    float4 inv = make_float4(1.f / tot.x, 1.f / tot.y, 1.f / tot.z, 1.f / tot.w);

    __half* w = g_w + (size_t)n * (BLOCK_IN * BLOCK_OUT);
#pragma unroll
    for (int j = 0; j < 8; j++) {
        int m = q * 8 + j;
        float4 e = *(const float4*)(se + m * 128 + o4);
        __half2 h01 = __floats2half2_rn(e.x * inv.x, e.y * inv.y);
        __half2 h23 = __floats2half2_rn(e.z * inv.z, e.w * inv.w);
        uint2 pk = make_uint2(*(uint32_t*)&h01, *(uint32_t*)&h23);
        *(uint2*)(w + m * 128 + o4) = pk;
    }
}

// ---------------------------------------------------------------------------
// Pass 2: R6 geometry (128 thr, 4 warps, warp tile 64x64, 2 CTAs/SM) with a
// half-tile (k-split) cp.async pipeline: raw fp32 x halves stream into a
// 32KB stage under the MMAs; short smem->smem converts refresh sA by column
// halves, which are disjoint from the columns being read.
// ---------------------------------------------------------------------------
#define LDA 136                          // halfs per padded sA/sB row
#define SB_BYTES   (128 * LDA * 2)       // 34816
#define SA_BYTES   (128 * LDA * 2)       // 34816
#define STAGE_BYTES 32768                // 128 rows x 64 k fp32, linear
#define SMEM_TOTAL (SB_BYTES + SA_BYTES + STAGE_BYTES)   // 102400
#define BT_PER_CTA 8

#define LDSM_X4(R0, R1, R2, R3, ADDR)                                          \
    asm volatile("ldmatrix.sync.aligned.m8n8.x4.shared.b16 {%0,%1,%2,%3}, [%4];" \
                 : "=r"(R0), "=r"(R1), "=r"(R2), "=r"(R3) : "r"(ADDR))

#define LDSM_X4_T(R0, R1, R2, R3, ADDR)                                        \
    asm volatile("ldmatrix.sync.aligned.m8n8.x4.trans.shared.b16 {%0,%1,%2,%3}, [%4];" \
                 : "=r"(R0), "=r"(R1), "=r"(R2), "=r"(R3) : "r"(ADDR))

#define MMA16816(D, A, B0, B1)                                                 \
    asm volatile("mma.sync.aligned.m16n8k16.row.col.f32.f16.f16.f32 "          \
                 "{%0,%1,%2,%3}, {%4,%5,%6,%7}, {%8,%9}, {%0,%1,%2,%3};"       \
                 : "+f"((D)[0]), "+f"((D)[1]), "+f"((D)[2]), "+f"((D)[3])      \
                 : "r"((A)[0]), "r"((A)[1]), "r"((A)[2]), "r"((A)[3]),         \
                   "r"(B0), "r"(B1))

__device__ __forceinline__ void cp16(uint32_t dst_smem, const void* src) {
    asm volatile("cp.async.cg.shared.global [%0], [%1], 16;" :: "r"(dst_smem), "l"(src));
}
#define CP_COMMIT() asm volatile("cp.async.commit_group;" ::: "memory")
#define CP_WAIT0()  asm volatile("cp.async.wait_group 0;" ::: "memory")

// stage one k-half of the x tile: 128 rows x 64 floats = 2048 16B chunks,
// 16 per thread (128 threads), linear layout in stage.
__device__ __forceinline__ void stage_half(const float* __restrict__ xb, int khalf,
                                           uint32_t stage_s, int tid) {
#pragma unroll
    for (int i = 0; i < 16; i++) {
        int idx = tid + i * 128;               // 0..2047
        int r   = idx >> 4;
        int k4  = (idx & 15) << 2;             // 0..60 within half
        cp16(stage_s + idx * 16, xb + (size_t)r * LAYER_IN + khalf * 64 + k4);
    }
}

// convert staged fp32 half -> fp16 sA columns [khalf*64, khalf*64+64)
__device__ __forceinline__ void convert_half(const float* stage, __half* sA, int khalf, int tid) {
#pragma unroll
    for (int i = 0; i < 16; i++) {
        int idx = tid + i * 128;
        float4 v = *(const float4*)(stage + idx * 4);
        int r  = idx >> 4;
        int k4 = (idx & 15) << 2;
        __half2 h01 = __floats2half2_rn(v.x, v.y);
        __half2 h23 = __floats2half2_rn(v.z, v.w);
        uint2 pk = make_uint2(*(uint32_t*)&h01, *(uint32_t*)&h23);
        *(uint2*)&sA[r * LDA + khalf * 64 + k4] = pk;
    }
}

__global__ __launch_bounds__(128, 2)
void gemm_kernel(const float* __restrict__ x, float* __restrict__ out) {
    extern __shared__ char smem[];
    __half* sB   = (__half*)smem;
    __half* sA   = (__half*)(smem + SB_BYTES);
    float* stage = (float*)(smem + SB_BYTES + SA_BYTES);
    const uint32_t stage_s = smem_u32(stage);

    const int tid  = threadIdx.x;
    const int wid  = tid >> 5;
    const int lane = tid & 31;
    const int n    = blockIdx.x;
    const int btg  = blockIdx.y;

    const float* xcol = x + (size_t)n * 128;

    // ---- prologue: w -> sB (LDG), first x tile -> sA (R6-style sync load) ----
    {
        const uint4* wsrc = (const uint4*)(g_w + (size_t)n * (BLOCK_IN * BLOCK_OUT));
#pragma unroll
        for (int i = 0; i < 16; i++) {
            int idx = tid + i * 128;
            int r   = idx >> 4;
            int c   = (idx & 15) << 3;
            *(uint4*)&sB[r * LDA + c] = wsrc[idx];
        }
    }
    {
        const float* xb = xcol + (size_t)(btg * BT_PER_CTA * 128) * LAYER_IN;
#pragma unroll
        for (int i = 0; i < 32; i++) {
            int idx = tid + i * 128;
            int r   = idx >> 5;
            int k4  = (idx & 31) << 2;
            float4 v = *(const float4*)(xb + (size_t)r * LAYER_IN + k4);
            __half2 h01 = __floats2half2_rn(v.x, v.y);
            __half2 h23 = __floats2half2_rn(v.z, v.w);
            uint2 pk = make_uint2(*(uint32_t*)&h01, *(uint32_t*)&h23);
            *(uint2*)&sA[r * LDA + k4] = pk;
        }
    }
    __syncthreads();

    const int warp_m = wid & 1;
    const int warp_n = wid >> 1;
    const int lr = lane & 15;
    const int lc = (lane >> 4) << 3;

    for (int t = 0; t < BT_PER_CTA; t++) {
        const int bt = btg * BT_PER_CTA + t;
        const bool pf = (t + 1 < BT_PER_CTA);
        const float* xnext = xcol + (size_t)((bt + 1) * 128) * LAYER_IN;

        // ---- issue k-half 0 of next tile; drains under ks0-3 ----
        if (pf) { stage_half(xnext, 0, stage_s, tid); CP_COMMIT(); }

        float acc[4][8][4];
#pragma unroll
        for (int mt = 0; mt < 4; mt++)
#pragma unroll
            for (int nt = 0; nt < 8; nt++)
#pragma unroll
                for (int j = 0; j < 4; j++) acc[mt][nt][j] = 0.f;

        // ---- ks 0..3: reads sA cols 0-63 ----
#pragma unroll
        for (int ks = 0; ks < 4; ks++) {
            const int k = ks * 16;
            uint32_t a[4][4];
#pragma unroll
            for (int mt = 0; mt < 4; mt++) {
                int row = warp_m * 64 + mt * 16 + lr;
                uint32_t addr = smem_u32(&sA[row * LDA + k + lc]);
                LDSM_X4(a[mt][0], a[mt][1], a[mt][2], a[mt][3], addr);
            }
            uint32_t b[8][2];
#pragma unroll
            for (int qq = 0; qq < 4; qq++) {
                int nn = warp_n * 64 + qq * 16;
                uint32_t addr = smem_u32(&sB[(k + lr) * LDA + nn + lc]);
                LDSM_X4_T(b[qq * 2][0], b[qq * 2][1], b[qq * 2 + 1][0], b[qq * 2 + 1][1], addr);
            }
#pragma unroll
            for (int mt = 0; mt < 4; mt++)
#pragma unroll
                for (int nt = 0; nt < 8; nt++)
                    MMA16816(acc[mt][nt], a[mt], b[nt][0], b[nt][1]);
        }

        // ---- mid: convert half0 into sA cols 0-63 (now next tile's data),
        //      then issue k-half 1; drains under ks4-7 ----
        if (pf) {
            CP_WAIT0();
            __syncthreads();                       // ks0-3 readers done w/ cols 0-63
            convert_half(stage, sA, 0, tid);       // disjoint from cols 64-127
            stage_half(xnext, 1, stage_s, tid);    // own chunks read before re-cp
            CP_COMMIT();
        }

        // ---- ks 4..7: reads sA cols 64-127 (still tile t) ----
#pragma unroll
        for (int ks = 4; ks < 8; ks++) {
            const int k = ks * 16;
            uint32_t a[4][4];
#pragma unroll
            for (int mt = 0; mt < 4; mt++) {
                int row = warp_m * 64 + mt * 16 + lr;
                uint32_t addr = smem_u32(&sA[row * LDA + k + lc]);
                LDSM_X4(a[mt][0], a[mt][1], a[mt][2], a[mt][3], addr);
            }
            uint32_t b[8][2];
#pragma unroll
            for (int qq = 0; qq < 4; qq++) {
                int nn = warp_n * 64 + qq * 16;
                uint32_t addr = smem_u32(&sB[(k + lr) * LDA + nn + lc]);
                LDSM_X4_T(b[qq * 2][0], b[qq * 2][1], b[qq * 2 + 1][0], b[qq * 2 + 1][1], addr);
            }
#pragma unroll
            for (int mt = 0; mt < 4; mt++)
#pragma unroll
                for (int nt = 0; nt < 8; nt++)
                    MMA16816(acc[mt][nt], a[mt], b[nt][0], b[nt][1]);
        }

        // ---- epilogue first (stores drain async under the wait/convert) ----
        float* obase = out + (size_t)(bt * 128) * LAYER_OUT + (size_t)n * 128;
        const int er = lane >> 2;
        const int ec = (lane & 3) << 1;
#pragma unroll
        for (int mt = 0; mt < 4; mt++) {
#pragma unroll
            for (int nt = 0; nt < 8; nt++) {
                int r0 = warp_m * 64 + mt * 16 + er;
                int c0 = warp_n * 64 + nt * 8 + ec;
                *(float2*)(obase + (size_t)r0 * LAYER_OUT + c0) =
                    make_float2(acc[mt][nt][0], acc[mt][nt][1]);
                *(float2*)(obase + (size_t)(r0 + 8) * LAYER_OUT + c0) =
                    make_float2(acc[mt][nt][2], acc[mt][nt][3]);
            }
        }

        // ---- tail: convert half1 into sA cols 64-127 ----
        if (pf) {
            CP_WAIT0();
            __syncthreads();                       // ks4-7 readers done w/ cols 64-127
            convert_half(stage, sA, 1, tid);
            __syncthreads();                       // sA fully tile t+1 before next ks0
        }
    }
}

// ---------------------------------------------------------------------------
extern "C" void kernel_launch(void* const* d_in, const int* in_sizes, int n_in,
                              void* d_out, int out_size) {
    (void)in_sizes; (void)n_in; (void)out_size;
    const float* x = (const float*)d_in[0];
    const float* c = (const float*)d_in[1];
    float* out = (float*)d_out;

    cudaFuncSetAttribute(softmax_kernel, cudaFuncAttributeMaxDynamicSharedMemorySize, 73728);
    cudaFuncSetAttribute(gemm_kernel,    cudaFuncAttributeMaxDynamicSharedMemorySize, SMEM_TOTAL);

    softmax_kernel<<<N_BLOCKS, 512, 73728>>>(c);
    gemm_kernel<<<dim3(N_BLOCKS, BATCH / 128 / BT_PER_CTA), 128, SMEM_TOTAL>>>(x, out);
}